// round 5
// baseline (speedup 1.0000x reference)
#include <cuda_runtime.h>
#include <stdint.h>
#include <math.h>

// ---------------------------------------------------------------------------
// Static device scratch (no runtime allocation anywhere).
// ---------------------------------------------------------------------------
#define BIG_ELEMS 44302336   // 4*64*416*416
__device__ float g_buf0[BIG_ELEMS];
__device__ float g_buf1[BIG_ELEMS];
__device__ float g_wdup[1500000];    // duplicated weights, all convs
__device__ float g_t[346112];        // 4*128*26*26
__device__ float g_w16a[16];
__device__ float g_w16b[16];
__device__ float g_bnsc[192];        // bn2 @0, bn4 @128
__device__ float g_bnsh[192];

// wdup offsets (floats): [ci][co][k(10, padded)] x2 duplicated
#define OFF_C1 0
#define OFF_C2 3840
#define OFF_C3 85760
#define OFF_C4 249600
#define OFF_D1 577280
#define OFF_D2 904960
#define OFF_D3 1232640
#define OFF_D4 1396480
#define OFF_D5 1478400

// ---------------------------------------------------------------------------
// f32x2 packed-math helpers
// ---------------------------------------------------------------------------
typedef unsigned long long ull;

__device__ __forceinline__ ull pack2(float lo, float hi) {
    ull r; asm("mov.b64 %0, {%1, %2};" : "=l"(r) : "f"(lo), "f"(hi)); return r;
}
__device__ __forceinline__ void unpack2(ull v, float& lo, float& hi) {
    asm("mov.b64 {%0, %1}, %2;" : "=f"(lo), "=f"(hi) : "l"(v));
}
__device__ __forceinline__ void fma2(ull& a, ull b, ull c) {
    asm("fma.rn.f32x2 %0, %1, %2, %0;" : "+l"(a) : "l"(b), "l"(c));
}

// ---------------------------------------------------------------------------
// cp.async helpers
// ---------------------------------------------------------------------------
__device__ __forceinline__ void cpa16(unsigned int dst, const float* src, bool ok) {
    asm volatile("cp.async.cg.shared.global [%0], [%1], 16, %2;\n"
                 :: "r"(dst), "l"(src), "r"(ok ? 16u : 0u));
}
__device__ __forceinline__ void cpa_commit() {
    asm volatile("cp.async.commit_group;\n");
}
template<int N>
__device__ __forceinline__ void cpa_wait() {
    asm volatile("cp.async.wait_group %0;\n" :: "n"(N));
}

// ---------------------------------------------------------------------------
// Weight duplication prep: wd[((ci*Co+co)*10+k)*2 + {0,1}] = w[(co*Cin+ci)*9+k]
// (k=9 is zero pad so each co-slot is 20 floats = 80B, 16B-aligned)
// ---------------------------------------------------------------------------
__global__ void wdup_k(const float* __restrict__ w, float* __restrict__ wd,
                       int Cin, int Co)
{
    int total = Cin * Co * 10;
    for (int i = blockIdx.x * blockDim.x + threadIdx.x; i < total;
         i += gridDim.x * blockDim.x) {
        int k  = i % 10;
        int co = (i / 10) % Co;
        int ci = i / (10 * Co);
        float v = (k < 9) ? w[((size_t)co * Cin + ci) * 9 + k] : 0.f;
        wd[2 * i]     = v;
        wd[2 * i + 1] = v;
    }
}

// ---------------------------------------------------------------------------
// Direct 3x3 conv, pad=1, stride=1, NCHW, fp32 (packed f32x2 math).
// 256 threads: tx=tid&7 (x4-wide), ty=tid>>3 -> 32x32 output tile.
// COPB output channels per block. 3-stage cp.async pipeline, 1 bar/ci.
// Weights pre-duplicated (LDS.128 -> two packed multiplicands).
// ACT: 0=none 1=relu 2=sigmoid; BN scale/shift after relu; POOL fuses 2x2 max.
// ---------------------------------------------------------------------------
template<int COPB, int ACT, bool BN, bool POOL>
__global__ void __launch_bounds__(256, 2)
conv3x3_k(const float* __restrict__ in, const float* __restrict__ wd,
          const float* __restrict__ bias, float* __restrict__ out,
          int N, int Cin, int Co, int H, int W,
          const float* __restrict__ bnsc, const float* __restrict__ bnsh)
{
    __shared__ __align__(16) float s_in[3][34 * 44];   // halo rows stride 44
    __shared__ __align__(16) float s_w[3][COPB * 20];

    const int tid = threadIdx.x;
    const int tx = tid & 7;
    const int ty = tid >> 3;
    const int tile_x = blockIdx.x * 32;
    const int tile_y = blockIdx.y * 32;
    const int co_blocks = Co / COPB;
    const int n   = blockIdx.z / co_blocks;
    const int co0 = (blockIdx.z % co_blocks) * COPB;

    // ---- hoisted halo addressing: 34 rows x 10 16B-chunks = 340 chunks ----
    int  h_off[2];  int h_sm[2];  bool h_ok[2];
#pragma unroll
    for (int k = 0; k < 2; k++) {
        int idx = tid + k * 256;
        h_ok[k] = false; h_off[k] = 0; h_sm[k] = 0;
        if (idx < 340) {
            int row = idx / 10, ch = idx % 10;
            int gy = tile_y - 1 + row;
            int gx = tile_x - 4 + ch * 4;          // 16B aligned; W%4==0 -> chunk all-in or all-out
            h_ok[k]  = (gy >= 0 && gy < H && gx >= 0 && gx < W);
            h_off[k] = h_ok[k] ? gy * W + gx : 0;
            h_sm[k]  = row * 44 + ch * 4;
        }
    }

    unsigned int s_in_a[3], s_w_a[3];
#pragma unroll
    for (int s = 0; s < 3; s++) {
        s_in_a[s] = (unsigned int)__cvta_generic_to_shared(&s_in[s][0]);
        s_w_a[s]  = (unsigned int)__cvta_generic_to_shared(&s_w[s][0]);
    }

    auto issue_stage = [&](int ci, int s) {
        const float* inC = in + ((size_t)n * Cin + ci) * (size_t)H * W;
#pragma unroll
        for (int k = 0; k < 2; k++)
            if (tid + k * 256 < 340)
                cpa16(s_in_a[s] + (unsigned int)h_sm[k] * 4u, inC + h_off[k], h_ok[k]);
        if (tid < COPB * 5)
            cpa16(s_w_a[s] + (unsigned int)tid * 16u,
                  wd + ((size_t)ci * Co + co0) * 20 + tid * 4, true);
        cpa_commit();
    };

    ull acc[COPB][2];
#pragma unroll
    for (int j = 0; j < COPB; j++) { acc[j][0] = 0ull; acc[j][1] = 0ull; }

    issue_stage(0, 0);
    if (Cin > 1) issue_stage(1, 1);

    for (int ci = 0; ci < Cin; ci++) {
        const int s = ci % 3;
        if (ci + 1 < Cin) cpa_wait<1>(); else cpa_wait<0>();
        __syncthreads();
        if (ci + 2 < Cin) issue_stage(ci + 2, (ci + 2) % 3);

        const float* si = s_in[s];
        // 3 input rows, 5 overlapping x-pairs each
        ull B[3][5];
#pragma unroll
        for (int r = 0; r < 3; r++) {
            const int base = (ty + r) * 44 + 4 * tx;
            float4 q0 = *(const float4*)&si[base];
            float4 q1 = *(const float4*)&si[base + 4];
            float  c8 = si[base + 8];
            B[r][0] = pack2(q0.w, q1.x);
            B[r][1] = pack2(q1.x, q1.y);
            B[r][2] = pack2(q1.y, q1.z);
            B[r][3] = pack2(q1.z, q1.w);
            B[r][4] = pack2(q1.w, c8);
        }

#pragma unroll
        for (int j = 0; j < COPB; j++) {
            const ulonglong2* wp = (const ulonglong2*)&s_w[s][j * 20];
            ulonglong2 w01 = wp[0], w23 = wp[1], w45 = wp[2], w67 = wp[3], w8x = wp[4];
            fma2(acc[j][0], B[0][0], w01.x); fma2(acc[j][1], B[0][2], w01.x);
            fma2(acc[j][0], B[0][1], w01.y); fma2(acc[j][1], B[0][3], w01.y);
            fma2(acc[j][0], B[0][2], w23.x); fma2(acc[j][1], B[0][4], w23.x);
            fma2(acc[j][0], B[1][0], w23.y); fma2(acc[j][1], B[1][2], w23.y);
            fma2(acc[j][0], B[1][1], w45.x); fma2(acc[j][1], B[1][3], w45.x);
            fma2(acc[j][0], B[1][2], w45.y); fma2(acc[j][1], B[1][4], w45.y);
            fma2(acc[j][0], B[2][0], w67.x); fma2(acc[j][1], B[2][2], w67.x);
            fma2(acc[j][0], B[2][1], w67.y); fma2(acc[j][1], B[2][3], w67.y);
            fma2(acc[j][0], B[2][2], w8x.x); fma2(acc[j][1], B[2][4], w8x.x);
        }
    }

    // ---- epilogue ----
    const int ox = tile_x + 4 * tx;
    const int oy = tile_y + ty;
#pragma unroll
    for (int j = 0; j < COPB; j++) {
        int co = co0 + j;
        float bv = __ldg(&bias[co]);
        float sc = 1.f, sh = 0.f;
        if (BN) { sc = __ldg(&bnsc[co]); sh = __ldg(&bnsh[co]); }
        float v0, v1, v2, v3;
        unpack2(acc[j][0], v0, v1);
        unpack2(acc[j][1], v2, v3);
        v0 += bv; v1 += bv; v2 += bv; v3 += bv;
        if (ACT == 1) {
            v0 = fmaxf(v0, 0.f); v1 = fmaxf(v1, 0.f);
            v2 = fmaxf(v2, 0.f); v3 = fmaxf(v3, 0.f);
        }
        if (BN) {
            v0 = v0 * sc + sh; v1 = v1 * sc + sh;
            v2 = v2 * sc + sh; v3 = v3 * sc + sh;
        }
        if (ACT == 2) {
            v0 = 1.f / (1.f + expf(-v0)); v1 = 1.f / (1.f + expf(-v1));
            v2 = 1.f / (1.f + expf(-v2)); v3 = 1.f / (1.f + expf(-v3));
        }
        if (POOL) {
            // vertical pool: row pair (ty even, ty odd) = lanes (l, l+8)
            float m0 = fmaxf(v0, __shfl_down_sync(0xffffffffu, v0, 8));
            float m1 = fmaxf(v1, __shfl_down_sync(0xffffffffu, v1, 8));
            float m2 = fmaxf(v2, __shfl_down_sync(0xffffffffu, v2, 8));
            float m3 = fmaxf(v3, __shfl_down_sync(0xffffffffu, v3, 8));
            if (!(tid & 8) && oy < H && ox < W) {
                float2 pv = make_float2(fmaxf(m0, m1), fmaxf(m2, m3));
                *(float2*)&out[((size_t)(n * Co + co) * (H >> 1) + (oy >> 1)) * (W >> 1) + (ox >> 1)] = pv;
            }
        } else {
            if (oy < H && ox < W)
                *(float4*)&out[((size_t)(n * Co + co) * H + oy) * W + ox] = make_float4(v0, v1, v2, v3);
        }
    }
}

// ---------------------------------------------------------------------------
// Bilinear 2x upsample, align_corners=True
// ---------------------------------------------------------------------------
__global__ void up2_k(const float* __restrict__ in, float* __restrict__ out,
                      int NC, int H, int W)
{
    int Ho = 2 * H, Wo = 2 * W;
    float sy = (float)(H - 1) / (float)(Ho - 1);
    float sx = (float)(W - 1) / (float)(Wo - 1);
    long total = (long)NC * Ho * Wo;
    for (long i = blockIdx.x * (long)blockDim.x + threadIdx.x; i < total;
         i += (long)gridDim.x * blockDim.x) {
        int xo = (int)(i % Wo);
        int yo = (int)((i / Wo) % Ho);
        long nc = i / ((long)Wo * Ho);
        float ys = yo * sy, xs = xo * sx;
        int y0 = (int)floorf(ys), x0 = (int)floorf(xs);
        int y1 = min(y0 + 1, H - 1), x1 = min(x0 + 1, W - 1);
        float wy = ys - (float)y0, wx = xs - (float)x0;
        const float* p = in + (size_t)nc * H * W;
        float a = p[y0 * W + x0] * (1.f - wy) + p[y1 * W + x0] * wy;
        float b = p[y0 * W + x1] * (1.f - wy) + p[y1 * W + x1] * wy;
        out[i] = a * (1.f - wx) + b * wx;
    }
}

// ---------------------------------------------------------------------------
// Block attention (two rounds fused algebraically):
//   wa[mn] = <x_mn, fold(x)>/676
//   wb[mn] = wa[mn] * <x_mn, fold_w(x, wa)>/676
//   y = x * wa[blk] * wb[blk]
// ---------------------------------------------------------------------------
__global__ void attn_t_k(const float* __restrict__ x, float* __restrict__ t,
                         const float* __restrict__ wgt)
{
    float wl[16];
#pragma unroll
    for (int i = 0; i < 16; i++) wl[i] = wgt ? __ldg(&wgt[i]) : 1.f;

    const int total = 4 * 128 * 26 * 26;
    for (int i = blockIdx.x * blockDim.x + threadIdx.x; i < total;
         i += gridDim.x * blockDim.x) {
        int w  = i % 26;
        int h  = (i / 26) % 26;
        int bc = i / 676;
        const float* p = x + (size_t)bc * 104 * 104;
        float s = 0.f;
#pragma unroll
        for (int k = 0; k < 4; k++)
#pragma unroll
            for (int l = 0; l < 4; l++)
                s += wl[k * 4 + l] * p[(k * 26 + h) * 104 + l * 26 + w];
        t[i] = s;
    }
}

__global__ void attn_w_k(const float* __restrict__ x, const float* __restrict__ t,
                         const float* __restrict__ premul, float* __restrict__ wout)
{
    const int mn = blockIdx.x;            // 16 blocks, one per weight
    const int m = mn >> 2, nn = mn & 3;
    const int total = 4 * 128 * 26 * 26;
    float s = 0.f;
    for (int i = threadIdx.x; i < total; i += blockDim.x) {
        int w  = i % 26;
        int h  = (i / 26) % 26;
        int bc = i / 676;
        s += x[(size_t)bc * 104 * 104 + (m * 26 + h) * 104 + nn * 26 + w] * t[i];
    }
    __shared__ float red[1024];
    red[threadIdx.x] = s;
    __syncthreads();
    for (int st = blockDim.x >> 1; st > 0; st >>= 1) {
        if (threadIdx.x < st) red[threadIdx.x] += red[threadIdx.x + st];
        __syncthreads();
    }
    if (threadIdx.x == 0) {
        float v = red[0] * (1.f / 676.f);
        if (premul) v *= premul[mn];
        wout[mn] = v;
    }
}

__global__ void attn_scale2_k(float* __restrict__ x, const float* __restrict__ wa,
                              const float* __restrict__ wb)
{
    const long total = 4L * 128 * 104 * 104;
    for (long i = blockIdx.x * (long)blockDim.x + threadIdx.x; i < total;
         i += (long)gridDim.x * blockDim.x) {
        int j  = (int)(i % 104);
        int ii = (int)((i / 104) % 104);
        int b  = (ii / 26) * 4 + (j / 26);
        x[i] *= wa[b] * wb[b];
    }
}

// ---------------------------------------------------------------------------
// Fold BN into per-channel scale/shift.
// ---------------------------------------------------------------------------
__global__ void bn_prep_k(const float* __restrict__ g, const float* __restrict__ b,
                          const float* __restrict__ m, const float* __restrict__ v,
                          float* __restrict__ sc, float* __restrict__ sh, int C)
{
    int c = blockIdx.x * blockDim.x + threadIdx.x;
    if (c < C) {
        float s = g[c] / sqrtf(v[c] + 1e-5f);
        sc[c] = s;
        sh[c] = b[c] - m[c] * s;
    }
}

// ---------------------------------------------------------------------------
// Host orchestration (graph-capturable: kernel launches only, default stream)
// ---------------------------------------------------------------------------
static inline dim3 conv_grid(int W, int H, int N, int Co, int copb)
{
    return dim3((W + 31) / 32, (H + 31) / 32, N * (Co / copb));
}

extern "C" void kernel_launch(void* const* d_in, const int* in_sizes, int n_in,
                              void* d_out, int out_size)
{
    (void)in_sizes; (void)n_in; (void)out_size;
    const float* x    = (const float*)d_in[0];
    const float* w1   = (const float*)d_in[1];
    const float* b1   = (const float*)d_in[2];
    const float* w2   = (const float*)d_in[3];
    const float* b2   = (const float*)d_in[4];
    const float* w3   = (const float*)d_in[5];
    const float* b3   = (const float*)d_in[6];
    const float* w4   = (const float*)d_in[7];
    const float* b4   = (const float*)d_in[8];
    const float* dw1  = (const float*)d_in[9];
    const float* db1  = (const float*)d_in[10];
    const float* dw2  = (const float*)d_in[11];
    const float* db2  = (const float*)d_in[12];
    const float* dw3  = (const float*)d_in[13];
    const float* db3  = (const float*)d_in[14];
    const float* dw4  = (const float*)d_in[15];
    const float* db4  = (const float*)d_in[16];
    const float* dw5  = (const float*)d_in[17];
    const float* db5  = (const float*)d_in[18];
    const float* bn2g = (const float*)d_in[19];
    const float* bn2b = (const float*)d_in[20];
    const float* bn2m = (const float*)d_in[21];
    const float* bn2v = (const float*)d_in[22];
    const float* bn4g = (const float*)d_in[23];
    const float* bn4b = (const float*)d_in[24];
    const float* bn4m = (const float*)d_in[25];
    const float* bn4v = (const float*)d_in[26];
    float* out = (float*)d_out;

    float *buf0, *buf1, *wd, *tb, *w16a, *w16b, *bnsc, *bnsh;
    cudaGetSymbolAddress((void**)&buf0, g_buf0);
    cudaGetSymbolAddress((void**)&buf1, g_buf1);
    cudaGetSymbolAddress((void**)&wd,   g_wdup);
    cudaGetSymbolAddress((void**)&tb,   g_t);
    cudaGetSymbolAddress((void**)&w16a, g_w16a);
    cudaGetSymbolAddress((void**)&w16b, g_w16b);
    cudaGetSymbolAddress((void**)&bnsc, g_bnsc);
    cudaGetSymbolAddress((void**)&bnsh, g_bnsh);

    // ---- prep: duplicated weights + folded BN (all independent, run first) ----
    wdup_k<<<16,  256>>>(w1,  wd + OFF_C1, 3,   64);
    wdup_k<<<160, 256>>>(w2,  wd + OFF_C2, 64,  64);
    wdup_k<<<320, 256>>>(w3,  wd + OFF_C3, 64,  128);
    wdup_k<<<640, 256>>>(w4,  wd + OFF_C4, 128, 128);
    wdup_k<<<640, 256>>>(dw1, wd + OFF_D1, 128, 128);
    wdup_k<<<640, 256>>>(dw2, wd + OFF_D2, 128, 128);
    wdup_k<<<320, 256>>>(dw3, wd + OFF_D3, 128, 64);
    wdup_k<<<160, 256>>>(dw4, wd + OFF_D4, 64,  64);
    wdup_k<<<8,   256>>>(dw5, wd + OFF_D5, 64,  2);
    bn_prep_k<<<1, 128>>>(bn2g, bn2b, bn2m, bn2v, bnsc,       bnsh,       128);
    bn_prep_k<<<1, 64 >>>(bn4g, bn4b, bn4m, bn4v, bnsc + 128, bnsh + 128, 64);

    // ---- encoder (pool fused into conv2/conv4 epilogues) ----
    conv3x3_k<8,1,false,false><<<conv_grid(416,416,4,64, 8), 256>>>(x,    wd+OFF_C1, b1, buf0, 4, 3,   64,  416, 416, nullptr, nullptr);
    conv3x3_k<8,1,false,true ><<<conv_grid(416,416,4,64, 8), 256>>>(buf0, wd+OFF_C2, b2, buf1, 4, 64,  64,  416, 416, nullptr, nullptr);
    conv3x3_k<8,1,false,false><<<conv_grid(208,208,4,128,8), 256>>>(buf1, wd+OFF_C3, b3, buf0, 4, 64,  128, 208, 208, nullptr, nullptr);
    conv3x3_k<8,1,false,true ><<<conv_grid(208,208,4,128,8), 256>>>(buf0, wd+OFF_C4, b4, buf1, 4, 128, 128, 208, 208, nullptr, nullptr);

    // ---- fused double block-attention on buf1 [4,128,104,104] ----
    attn_t_k<<<1352, 256>>>(buf1, tb, nullptr);
    attn_w_k<<<16, 1024>>>(buf1, tb, nullptr, w16a);
    attn_t_k<<<1352, 256>>>(buf1, tb, w16a);
    attn_w_k<<<16, 1024>>>(buf1, tb, w16a, w16b);
    attn_scale2_k<<<2048, 256>>>(buf1, w16a, w16b);

    // ---- decoder ----
    conv3x3_k<8,1,false,false><<<conv_grid(104,104,4,128,8), 256>>>(buf1, wd+OFF_D1, db1, buf0, 4, 128, 128, 104, 104, nullptr, nullptr);
    conv3x3_k<8,1,true ,false><<<conv_grid(104,104,4,128,8), 256>>>(buf0, wd+OFF_D2, db2, buf1, 4, 128, 128, 104, 104, bnsc, bnsh);
    up2_k<<<2048, 256>>>(buf1, buf0, 4 * 128, 104, 104);
    conv3x3_k<8,1,false,false><<<conv_grid(208,208,4,64, 8), 256>>>(buf0, wd+OFF_D3, db3, buf1, 4, 128, 64,  208, 208, nullptr, nullptr);
    conv3x3_k<8,1,true ,false><<<conv_grid(208,208,4,64, 8), 256>>>(buf1, wd+OFF_D4, db4, buf0, 4, 64,  64,  208, 208, bnsc + 128, bnsh + 128);
    up2_k<<<4096, 256>>>(buf0, buf1, 4 * 64, 208, 208);
    conv3x3_k<2,2,false,false><<<conv_grid(416,416,4,2,  2), 256>>>(buf1, wd+OFF_D5, db5, out, 4, 64,  2,   416, 416, nullptr, nullptr);
}